// round 1
// baseline (speedup 1.0000x reference)
#include <cuda_runtime.h>
#include <math.h>

// Problem constants
#define BB   4096
#define HH   1024
#define H2   2048
#define NSTEPS 10

// ---------------- static device scratch (no allocations allowed) ----------------
__device__ __align__(16) float g_x1[(size_t)BB * H2];     // 32 MB  activations layer1 (tf32-rounded)
__device__ __align__(16) float g_x2[(size_t)BB * H2];     // 32 MB  activations layer2 (tf32-rounded)
__device__ __align__(16) float g_h   [(size_t)BB * HH];   // 16 MB  RK4 state (fp32 exact)
__device__ __align__(16) float g_hr  [(size_t)BB * HH];   // 16 MB  rounded copy of state (MMA A input)
__device__ __align__(16) float g_htmp[(size_t)BB * HH];   // 16 MB  h + c*k (tf32-rounded, MMA A input)
__device__ __align__(16) float g_acc [(size_t)BB * HH];   // 16 MB  k1+2k2+2k3 accumulator (fp32 exact)
__device__ __align__(16) float g_W1r[(size_t)HH * H2];    // 8 MB   rounded weights
__device__ __align__(16) float g_W2r[(size_t)H2 * H2];    // 16 MB
__device__ __align__(16) float g_W3r[(size_t)H2 * HH];    // 8 MB

// Round fp32 -> tf32 (round-to-nearest via +half-ulp of the 13 dropped bits).
__device__ __forceinline__ float tf32r(float x) {
    unsigned u = __float_as_uint(x);
    u += 0x1000u;
    u &= 0xFFFFE000u;
    return __uint_as_float(u);
}

// tanh via exp: accurate to ~1e-6 rel, much cheaper than tanhf.
__device__ __forceinline__ float ftanh(float x) {
    float e = __expf(2.0f * x);
    return 1.0f - __fdividef(2.0f, e + 1.0f);
}

// ---------------- helper kernels ----------------
__global__ void round_copy(const float* __restrict__ src, float* __restrict__ dst, int n) {
    int i = blockIdx.x * blockDim.x + threadIdx.x;
    int stride = gridDim.x * blockDim.x;
    for (; i < n; i += stride) dst[i] = tf32r(src[i]);
}

__global__ void init_h(const float* __restrict__ h0, float* __restrict__ h,
                       float* __restrict__ hr, int n) {
    int i = blockIdx.x * blockDim.x + threadIdx.x;
    int stride = gridDim.x * blockDim.x;
    for (; i < n; i += stride) {
        float v = h0[i];
        h[i] = v;
        hr[i] = tf32r(v);
    }
}

// ---------------- fused TF32 GEMM (mma.sync m16n8k8) ----------------
// C(M=4096, N, K): A row-major (lda=K), Bw row-major (ldb=N). Operands are
// pre-rounded to tf32. Epilogues:
//  MODE 0: out = tf32r(tanh(c + bias[n] + tval*wlast[n]))   (layer1 incl. time column)
//  MODE 1: out = tf32r(tanh(c + bias[n]))                   (layer2)
//  MODE 2: k = c+bias; out2(acc)=k;              out(htmp)=tf32r(hin + c0*k)   (k1)
//  MODE 3: k = c+bias; out2(acc)=accin + c1*k;   out(htmp)=tf32r(hin + c0*k)   (k2,k3)
//  MODE 4: k = c+bias; v = hin + c0*(accin + k); out=v; out2(hr)=tf32r(v)      (k4 / step combine)
template <int N, int K, int MODE>
__global__ void __launch_bounds__(256, 2) gemm_tf32(
    const float* __restrict__ A, const float* __restrict__ Bw,
    const float* __restrict__ bias, const float* __restrict__ wlast, float tval,
    const float* __restrict__ hin, const float* __restrict__ accin,
    float* __restrict__ out, float* __restrict__ out2,
    float c0, float c1)
{
    constexpr int LAS = 20;    // As stride (floats): conflict-free, float4-aligned
    constexpr int LBS = 136;   // Bs stride (floats): conflict-free, float4-aligned
    __shared__ __align__(16) float As[128 * LAS];
    __shared__ __align__(16) float Bs[16 * LBS];

    const int tid = threadIdx.x;
    const int bM = blockIdx.y * 128;
    const int bN = blockIdx.x * 128;

    // global -> smem load mapping (float4)
    const int arow = tid >> 2;            // 0..63  (rows arow, arow+64)
    const int acol = (tid & 3) << 2;      // 0,4,8,12
    const int brow = tid >> 5;            // 0..7   (rows brow, brow+8)
    const int bcol = (tid & 31) << 2;     // 0..124

    const float* Ap = A + (size_t)(bM + arow) * K + acol;
    const float* Bp = Bw + (size_t)brow * N + bN + bcol;

    float4 ra0 = *(const float4*)Ap;
    float4 ra1 = *(const float4*)(Ap + (size_t)64 * K);
    float4 rb0 = *(const float4*)Bp;
    float4 rb1 = *(const float4*)(Bp + (size_t)8 * N);

    *(float4*)&As[arow * LAS + acol] = ra0;
    *(float4*)&As[(arow + 64) * LAS + acol] = ra1;
    *(float4*)&Bs[brow * LBS + bcol] = rb0;
    *(float4*)&Bs[(brow + 8) * LBS + bcol] = rb1;
    __syncthreads();

    const int warp = tid >> 5;
    const int lane = tid & 31;
    const int gp = lane >> 2;   // 0..7
    const int tg = lane & 3;    // 0..3
    const int wRow = (warp & 1) * 64;    // 2 warps along M -> warp tile 64x32
    const int wCol = (warp >> 1) * 32;   // 4 warps along N

    float acc[4][4][4];
#pragma unroll
    for (int mi = 0; mi < 4; ++mi)
#pragma unroll
        for (int ni = 0; ni < 4; ++ni)
#pragma unroll
            for (int r = 0; r < 4; ++r) acc[mi][ni][r] = 0.0f;

    const int KT = K / 16;
    for (int kt = 0; kt < KT; ++kt) {
        const bool hasNext = (kt + 1 < KT);
        if (hasNext) {
            Ap += 16;
            Bp += (size_t)16 * N;
            ra0 = *(const float4*)Ap;
            ra1 = *(const float4*)(Ap + (size_t)64 * K);
            rb0 = *(const float4*)Bp;
            rb1 = *(const float4*)(Bp + (size_t)8 * N);
        }
#pragma unroll
        for (int kk = 0; kk < 16; kk += 8) {
            float a[4][4];
            float b[4][2];
#pragma unroll
            for (int mi = 0; mi < 4; ++mi) {
                const float* p = &As[(wRow + mi * 16 + gp) * LAS + kk + tg];
                a[mi][0] = p[0];
                a[mi][1] = p[8 * LAS];
                a[mi][2] = p[4];
                a[mi][3] = p[8 * LAS + 4];
            }
#pragma unroll
            for (int ni = 0; ni < 4; ++ni) {
                const float* p = &Bs[(kk + tg) * LBS + wCol + ni * 8 + gp];
                b[ni][0] = p[0];
                b[ni][1] = p[4 * LBS];
            }
#pragma unroll
            for (int mi = 0; mi < 4; ++mi)
#pragma unroll
                for (int ni = 0; ni < 4; ++ni) {
                    asm("mma.sync.aligned.m16n8k8.row.col.f32.tf32.tf32.f32 "
                        "{%0,%1,%2,%3}, {%4,%5,%6,%7}, {%8,%9}, {%0,%1,%2,%3};\n"
                        : "+f"(acc[mi][ni][0]), "+f"(acc[mi][ni][1]),
                          "+f"(acc[mi][ni][2]), "+f"(acc[mi][ni][3])
                        : "r"(__float_as_uint(a[mi][0])), "r"(__float_as_uint(a[mi][1])),
                          "r"(__float_as_uint(a[mi][2])), "r"(__float_as_uint(a[mi][3])),
                          "r"(__float_as_uint(b[ni][0])), "r"(__float_as_uint(b[ni][1])));
                }
        }
        __syncthreads();
        if (hasNext) {
            *(float4*)&As[arow * LAS + acol] = ra0;
            *(float4*)&As[(arow + 64) * LAS + acol] = ra1;
            *(float4*)&Bs[brow * LBS + bcol] = rb0;
            *(float4*)&Bs[(brow + 8) * LBS + bcol] = rb1;
            __syncthreads();
        }
    }

    // ---------------- epilogue ----------------
#pragma unroll
    for (int mi = 0; mi < 4; ++mi) {
#pragma unroll
        for (int half = 0; half < 2; ++half) {
            const int row = bM + wRow + mi * 16 + gp + half * 8;
#pragma unroll
            for (int ni = 0; ni < 4; ++ni) {
                const int col = bN + wCol + ni * 8 + 2 * tg;
                const size_t idx = (size_t)row * N + col;
                float v0 = acc[mi][ni][half * 2 + 0];
                float v1 = acc[mi][ni][half * 2 + 1];

                if (MODE == 0 || MODE == 1) {
                    float bb0 = bias[col], bb1 = bias[col + 1];
                    if (MODE == 0) {
                        bb0 += tval * wlast[col];
                        bb1 += tval * wlast[col + 1];
                    }
                    float2 o;
                    o.x = tf32r(ftanh(v0 + bb0));
                    o.y = tf32r(ftanh(v1 + bb1));
                    *(float2*)&out[idx] = o;
                } else {
                    const float k0 = v0 + bias[col];
                    const float k1v = v1 + bias[col + 1];
                    const float2 hv = *(const float2*)&hin[idx];
                    if (MODE == 2) {
                        float2 av;
                        av.x = k0; av.y = k1v;
                        *(float2*)&out2[idx] = av;
                        float2 o;
                        o.x = tf32r(hv.x + c0 * k0);
                        o.y = tf32r(hv.y + c0 * k1v);
                        *(float2*)&out[idx] = o;
                    } else if (MODE == 3) {
                        float2 av = *(const float2*)&accin[idx];
                        av.x += c1 * k0; av.y += c1 * k1v;
                        *(float2*)&out2[idx] = av;
                        float2 o;
                        o.x = tf32r(hv.x + c0 * k0);
                        o.y = tf32r(hv.y + c0 * k1v);
                        *(float2*)&out[idx] = o;
                    } else {  // MODE 4
                        const float2 av = *(const float2*)&accin[idx];
                        float2 o;
                        o.x = hv.x + c0 * (av.x + k0);
                        o.y = hv.y + c0 * (av.y + k1v);
                        *(float2*)&out[idx] = o;
                        float2 r;
                        r.x = tf32r(o.x);
                        r.y = tf32r(o.y);
                        *(float2*)&out2[idx] = r;
                    }
                }
            }
        }
    }
}

// ---------------- host launch ----------------
extern "C" void kernel_launch(void* const* d_in, const int* in_sizes, int n_in,
                              void* d_out, int out_size)
{
    (void)in_sizes; (void)n_in; (void)out_size;
    const float* h0 = (const float*)d_in[0];
    const float* W1 = (const float*)d_in[1];
    const float* b1 = (const float*)d_in[2];
    const float* W2 = (const float*)d_in[3];
    const float* b2 = (const float*)d_in[4];
    const float* W3 = (const float*)d_in[5];
    const float* b3 = (const float*)d_in[6];
    float* outp = (float*)d_out;

    float *x1, *x2, *h, *hr, *htmp, *acc, *w1r, *w2r, *w3r;
    cudaGetSymbolAddress((void**)&x1, g_x1);
    cudaGetSymbolAddress((void**)&x2, g_x2);
    cudaGetSymbolAddress((void**)&h, g_h);
    cudaGetSymbolAddress((void**)&hr, g_hr);
    cudaGetSymbolAddress((void**)&htmp, g_htmp);
    cudaGetSymbolAddress((void**)&acc, g_acc);
    cudaGetSymbolAddress((void**)&w1r, g_W1r);
    cudaGetSymbolAddress((void**)&w2r, g_W2r);
    cudaGetSymbolAddress((void**)&w3r, g_W3r);

    // Pre-round weights to tf32 once per call (deterministic).
    round_copy<<<2048, 256>>>(W1, w1r, HH * H2);          // rows 0..1023 of W1
    round_copy<<<2048, 256>>>(W2, w2r, H2 * H2);
    round_copy<<<2048, 256>>>(W3, w3r, H2 * HH);
    init_h<<<2048, 256>>>(h0, h, hr, BB * HH);

    const float* wlast = W1 + (size_t)HH * H2;  // time-column row of W1

    dim3 blk(256);
    dim3 g1(H2 / 128, BB / 128);  // 16 x 32 (N=2048)
    dim3 g3(HH / 128, BB / 128);  // 8 x 32  (N=1024)

    const float step = 1.0f / 10.0f;
    for (int i = 0; i < NSTEPS; ++i) {
        const float ti = (float)i * step;
        const float tn = (float)(i + 1) * step;
        const float dt = tn - ti;
        const float th = ti + 0.5f * dt;
        const float dt2 = 0.5f * dt;
        const float dt6 = dt / 6.0f;
        float* hOut = (i == NSTEPS - 1) ? outp : h;

        // ---- k1 = f(ti, h) ----
        gemm_tf32<H2, HH, 0><<<g1, blk>>>(hr, w1r, b1, wlast, ti, nullptr, nullptr, x1, nullptr, 0.f, 0.f);
        gemm_tf32<H2, H2, 1><<<g1, blk>>>(x1, w2r, b2, nullptr, 0.f, nullptr, nullptr, x2, nullptr, 0.f, 0.f);
        gemm_tf32<HH, H2, 2><<<g3, blk>>>(x2, w3r, b3, nullptr, 0.f, h, nullptr, htmp, acc, dt2, 0.f);

        // ---- k2 = f(ti+dt/2, h + dt/2*k1) ----
        gemm_tf32<H2, HH, 0><<<g1, blk>>>(htmp, w1r, b1, wlast, th, nullptr, nullptr, x1, nullptr, 0.f, 0.f);
        gemm_tf32<H2, H2, 1><<<g1, blk>>>(x1, w2r, b2, nullptr, 0.f, nullptr, nullptr, x2, nullptr, 0.f, 0.f);
        gemm_tf32<HH, H2, 3><<<g3, blk>>>(x2, w3r, b3, nullptr, 0.f, h, acc, htmp, acc, dt2, 2.0f);

        // ---- k3 = f(ti+dt/2, h + dt/2*k2) ----
        gemm_tf32<H2, HH, 0><<<g1, blk>>>(htmp, w1r, b1, wlast, th, nullptr, nullptr, x1, nullptr, 0.f, 0.f);
        gemm_tf32<H2, H2, 1><<<g1, blk>>>(x1, w2r, b2, nullptr, 0.f, nullptr, nullptr, x2, nullptr, 0.f, 0.f);
        gemm_tf32<HH, H2, 3><<<g3, blk>>>(x2, w3r, b3, nullptr, 0.f, h, acc, htmp, acc, dt, 2.0f);

        // ---- k4 = f(ti+dt, h + dt*k3); h += dt/6*(k1+2k2+2k3+k4) ----
        gemm_tf32<H2, HH, 0><<<g1, blk>>>(htmp, w1r, b1, wlast, tn, nullptr, nullptr, x1, nullptr, 0.f, 0.f);
        gemm_tf32<H2, H2, 1><<<g1, blk>>>(x1, w2r, b2, nullptr, 0.f, nullptr, nullptr, x2, nullptr, 0.f, 0.f);
        gemm_tf32<HH, H2, 4><<<g3, blk>>>(x2, w3r, b3, nullptr, 0.f, h, acc, hOut, hr, dt6, 0.f);
    }
}